// round 6
// baseline (speedup 1.0000x reference)
#include <cuda_runtime.h>
#include <math.h>
#include <stdint.h>

#define N_TOK 8192
#define DM    1024
#define DFF   4096
#define NE    8
#define TOPK  2
#define CAP   1280
#define PAD   36          // smem row stride in floats
#define SROWB 144         // row stride bytes
#define SSTAGE 55296      // bytes per pipeline stage (384 rows x 144B)
#define NSTAGE 4

// ---------------- scratch ----------------
__device__ float g_buf[2 * NE * CAP * DM];
__device__ float g_h  [2 * NE * CAP * DFF];
__device__ float g_ob [2 * NE * CAP * DM];
__device__ float g_probs[N_TOK * NE];
__device__ int   g_top_idx[N_TOK * TOPK];
__device__ float g_top_w [N_TOK * TOPK];
__device__ int   g_pos   [N_TOK * TOPK];
__device__ int   g_cnt   [TOPK * NE];

// ---------------- helpers ----------------
__device__ __forceinline__ uint32_t smem_u32(const void* p) {
    uint32_t a;
    asm("{ .reg .u64 t; cvta.to.shared.u64 t, %1; cvt.u32.u64 %0, t; }" : "=r"(a) : "l"(p));
    return a;
}
__device__ __forceinline__ float tf32f(float x) {
    uint32_t r; asm("cvt.rna.tf32.f32 %0, %1;" : "=r"(r) : "f"(x));
    return __uint_as_float(r);
}
__device__ __forceinline__ uint32_t tf32u(float x) {
    uint32_t r; asm("cvt.rna.tf32.f32 %0, %1;" : "=r"(r) : "f"(x));
    return r;
}
__device__ __forceinline__ void mma_tf32(float* c, const uint32_t* a, uint32_t b0, uint32_t b1) {
    asm volatile(
        "mma.sync.aligned.m16n8k8.row.col.f32.tf32.tf32.f32 "
        "{%0,%1,%2,%3}, {%4,%5,%6,%7}, {%8,%9}, {%0,%1,%2,%3};"
        : "+f"(c[0]), "+f"(c[1]), "+f"(c[2]), "+f"(c[3])
        : "r"(a[0]), "r"(a[1]), "r"(a[2]), "r"(a[3]), "r"(b0), "r"(b1));
}
__device__ __forceinline__ void cp16(uint32_t s, const void* g) {
    asm volatile("cp.async.cg.shared.global [%0], [%1], 16;" :: "r"(s), "l"(g) : "memory");
}
#define CP_COMMIT() asm volatile("cp.async.commit_group;" ::: "memory")
#define CP_WAIT2()  asm volatile("cp.async.wait_group 2;" ::: "memory")

// ---------------- 1. router ----------------
__global__ __launch_bounds__(256) void router_kernel(const float* __restrict__ x,
                                                     const float* __restrict__ gw) {
    int warp = (blockIdx.x * blockDim.x + threadIdx.x) >> 5;
    int lane = threadIdx.x & 31;
    if (warp >= N_TOK) return;
    const float* xr = x + (size_t)warp * DM;
    float acc[NE];
#pragma unroll
    for (int e = 0; e < NE; e++) acc[e] = 0.f;
    for (int i = lane; i < DM; i += 32) {
        float xv = xr[i];
#pragma unroll
        for (int e = 0; e < NE; e++) acc[e] += xv * gw[e * DM + i];
    }
#pragma unroll
    for (int off = 16; off > 0; off >>= 1)
#pragma unroll
        for (int e = 0; e < NE; e++) acc[e] += __shfl_xor_sync(0xffffffffu, acc[e], off);
    if (lane == 0) {
        float mx = acc[0];
#pragma unroll
        for (int e = 1; e < NE; e++) mx = fmaxf(mx, acc[e]);
        float p[NE], s = 0.f;
#pragma unroll
        for (int e = 0; e < NE; e++) { p[e] = expf(acc[e] - mx); s += p[e]; }
        float inv = 1.f / s;
        int i0 = 0;
#pragma unroll
        for (int e = 1; e < NE; e++) if (p[e] > p[i0]) i0 = e;
        int i1 = (i0 == 0) ? 1 : 0;
#pragma unroll
        for (int e = 0; e < NE; e++) if (e != i0 && e != i1 && p[e] > p[i1]) i1 = e;
#pragma unroll
        for (int e = 0; e < NE; e++) g_probs[warp * NE + e] = p[e] * inv;
        float p0 = p[i0] * inv, p1 = p[i1] * inv;
        float ws = p0 + p1 + 1e-10f;
        g_top_idx[warp * 2 + 0] = i0;  g_top_w[warp * 2 + 0] = p0 / ws;
        g_top_idx[warp * 2 + 1] = i1;  g_top_w[warp * 2 + 1] = p1 / ws;
    }
}

// ---------------- 2. capacity scan ----------------
__global__ __launch_bounds__(256) void scan_kernel() {
    int k = blockIdx.x;
    int t = threadIdx.x;
    const int CH = N_TOK / 256;
    __shared__ int cnt[256][NE];
    int local[NE];
#pragma unroll
    for (int e = 0; e < NE; e++) local[e] = 0;
    for (int i = 0; i < CH; i++) local[g_top_idx[(t * CH + i) * 2 + k]]++;
#pragma unroll
    for (int e = 0; e < NE; e++) cnt[t][e] = local[e];
    __syncthreads();
    if (t < NE) {
        int run = 0;
        for (int i = 0; i < 256; i++) { int v = cnt[i][t]; cnt[i][t] = run; run += v; }
        g_cnt[k * NE + t] = run;
    }
    __syncthreads();
    int off[NE];
#pragma unroll
    for (int e = 0; e < NE; e++) off[e] = cnt[t][e];
    for (int i = 0; i < CH; i++) {
        int tk = (t * CH + i) * 2 + k;
        g_pos[tk] = off[g_top_idx[tk]]++;
    }
}

// ---------------- 3. gather (tf32 rounding of A at write) ----------------
__global__ __launch_bounds__(256) void gather_kernel(const float* __restrict__ x) {
    int tk = blockIdx.x;
    int pos = g_pos[tk];
    if (pos >= CAP) return;
    int e = g_top_idx[tk];
    int k = tk & 1, t = tk >> 1;
    float4*       dst = (float4*)(g_buf + ((size_t)(k * NE + e) * CAP + pos) * DM);
    const float4* src = (const float4*)(x + (size_t)t * DM);
    float4 v = src[threadIdx.x];
    v.x = tf32f(v.x); v.y = tf32f(v.y); v.z = tf32f(v.z); v.w = tf32f(v.w);
    dst[threadIdx.x] = v;
}

// ---------------- 4. gemm13: 128M x 128N(x2), warp 64x32(x2), 4-stage, 1 barrier/chunk ----------------
__global__ __launch_bounds__(256) void gemm13_mma(const float* __restrict__ W1,
                                                  const float* __restrict__ W3) {
    int z = blockIdx.z, e = z & (NE - 1);
    int rows = g_cnt[z]; if (rows > CAP) rows = CAP;
    int m0 = blockIdx.y * 128; if (m0 >= rows) return;
    int n0 = blockIdx.x * 128;

    extern __shared__ char dsm[];
    uint32_t sb = smem_u32(dsm);

    const float* gA  = g_buf + (size_t)z * CAP * DM + (size_t)m0 * DM;
    const float* gB1 = W1 + (size_t)e * DFF * DM + (size_t)n0 * DM;
    const float* gB3 = W3 + (size_t)e * DFF * DM + (size_t)n0 * DM;

    int tid = threadIdx.x, wid = tid >> 5, lane = tid & 31;
    int wm = wid >> 2, wn = wid & 3;
    int g = lane >> 2, tg = lane & 3;

    auto issue = [&](int c) {
        uint32_t st = sb + (uint32_t)(c % NSTAGE) * SSTAGE;
        int k0 = c * 32;
#pragma unroll
        for (int i = 0; i < 4; i++) {
            int f = tid + i * 256, r = f >> 3, c4 = f & 7;
            cp16(st + r * SROWB + c4 * 16, gA + (size_t)r * DM + k0 + c4 * 4);
        }
#pragma unroll
        for (int i = 0; i < 4; i++) {
            int f = tid + i * 256, r = f >> 3, c4 = f & 7;
            cp16(st + 18432u + r * SROWB + c4 * 16, gB1 + (size_t)r * DM + k0 + c4 * 4);
        }
#pragma unroll
        for (int i = 0; i < 4; i++) {
            int f = tid + i * 256, r = f >> 3, c4 = f & 7;
            cp16(st + 36864u + r * SROWB + c4 * 16, gB3 + (size_t)r * DM + k0 + c4 * 4);
        }
    };

    float acc1[4][4][4], acc2[4][4][4];
#pragma unroll
    for (int mi = 0; mi < 4; mi++)
#pragma unroll
        for (int ni = 0; ni < 4; ni++)
#pragma unroll
            for (int r = 0; r < 4; r++) { acc1[mi][ni][r] = 0.f; acc2[mi][ni][r] = 0.f; }

    uint32_t af[2][4][4], b1f[2][4][2], b3f[2][4][2];

    // A already tf32-rounded in memory; B rounded here in-register (off critical path)
    auto loadfrag = [&](const float* As, const float* B1s, const float* B3s, int kk, int buf) {
        int k = kk * 8;
#pragma unroll
        for (int mi = 0; mi < 4; mi++) {
            int mb = wm * 64 + mi * 16;
            af[buf][mi][0] = __float_as_uint(As[(mb + g) * PAD + k + tg]);
            af[buf][mi][1] = __float_as_uint(As[(mb + 8 + g) * PAD + k + tg]);
            af[buf][mi][2] = __float_as_uint(As[(mb + g) * PAD + k + 4 + tg]);
            af[buf][mi][3] = __float_as_uint(As[(mb + 8 + g) * PAD + k + 4 + tg]);
        }
#pragma unroll
        for (int ni = 0; ni < 4; ni++) {
            int nb = wn * 32 + ni * 8;
            b1f[buf][ni][0] = tf32u(B1s[(nb + g) * PAD + k + tg]);
            b1f[buf][ni][1] = tf32u(B1s[(nb + g) * PAD + k + 4 + tg]);
            b3f[buf][ni][0] = tf32u(B3s[(nb + g) * PAD + k + tg]);
            b3f[buf][ni][1] = tf32u(B3s[(nb + g) * PAD + k + 4 + tg]);
        }
    };

    const int NC = DM / 32;   // 32
    issue(0); CP_COMMIT();
    issue(1); CP_COMMIT();
    issue(2); CP_COMMIT();

    for (int c = 0; c < NC; c++) {
        CP_WAIT2();
        __syncthreads();                  // single barrier per chunk
        if (c + 3 < NC) issue(c + 3);
        CP_COMMIT();
        const float* As  = (const float*)(dsm + (c % NSTAGE) * SSTAGE);
        const float* B1s = As + 18432 / 4;
        const float* B3s = As + 36864 / 4;
        loadfrag(As, B1s, B3s, 0, 0);
#pragma unroll
        for (int kk = 0; kk < 4; kk++) {
            int cur = kk & 1;
            if (kk < 3) loadfrag(As, B1s, B3s, kk + 1, cur ^ 1);
#pragma unroll
            for (int ni = 0; ni < 4; ni++) {
#pragma unroll
                for (int mi = 0; mi < 4; mi++)
                    mma_tf32(acc1[mi][ni], af[cur][mi], b1f[cur][ni][0], b1f[cur][ni][1]);
#pragma unroll
                for (int mi = 0; mi < 4; mi++)
                    mma_tf32(acc2[mi][ni], af[cur][mi], b3f[cur][ni][0], b3f[cur][ni][1]);
            }
        }
    }

    float* H = g_h + (size_t)z * CAP * DFF;
#pragma unroll
    for (int mi = 0; mi < 4; mi++)
#pragma unroll
        for (int half = 0; half < 2; half++) {
            int m = m0 + wm * 64 + mi * 16 + half * 8 + g;
            if (m < rows) {
#pragma unroll
                for (int ni = 0; ni < 4; ni++) {
                    float v0 = acc1[mi][ni][half * 2 + 0];
                    float v1 = acc1[mi][ni][half * 2 + 1];
                    float o0 = tf32f((v0 / (1.f + expf(-v0))) * acc2[mi][ni][half * 2 + 0]);
                    float o1 = tf32f((v1 / (1.f + expf(-v1))) * acc2[mi][ni][half * 2 + 1]);
                    int col = n0 + wn * 32 + ni * 8 + 2 * tg;
                    *(float2*)&H[(size_t)m * DFF + col] = make_float2(o0, o1);
                }
            }
        }
}

// ---------------- 5. gemm2: 128M x 256N, warp 64x64, 4-stage, 1 barrier/chunk ----------------
__global__ __launch_bounds__(256) void gemm2_mma(const float* __restrict__ W2) {
    int z = blockIdx.z, e = z & (NE - 1);
    int rows = g_cnt[z]; if (rows > CAP) rows = CAP;
    int m0 = blockIdx.y * 128; if (m0 >= rows) return;
    int n0 = blockIdx.x * 256;

    extern __shared__ char dsm[];
    uint32_t sb = smem_u32(dsm);

    const float* gA = g_h + (size_t)z * CAP * DFF + (size_t)m0 * DFF;
    const float* gB = W2  + (size_t)e * DM * DFF + (size_t)n0 * DFF;

    int tid = threadIdx.x, wid = tid >> 5, lane = tid & 31;
    int wm = wid >> 2, wn = wid & 3;
    int g = lane >> 2, tg = lane & 3;

    auto issue = [&](int c) {
        uint32_t st = sb + (uint32_t)(c % NSTAGE) * SSTAGE;
        int k0 = c * 32;
#pragma unroll
        for (int i = 0; i < 4; i++) {
            int f = tid + i * 256, r = f >> 3, c4 = f & 7;
            cp16(st + r * SROWB + c4 * 16, gA + (size_t)r * DFF + k0 + c4 * 4);
        }
#pragma unroll
        for (int i = 0; i < 8; i++) {
            int f = tid + i * 256, r = f >> 3, c4 = f & 7;
            cp16(st + 18432u + r * SROWB + c4 * 16, gB + (size_t)r * DFF + k0 + c4 * 4);
        }
    };

    float acc[4][8][4];
#pragma unroll
    for (int mi = 0; mi < 4; mi++)
#pragma unroll
        for (int ni = 0; ni < 8; ni++)
#pragma unroll
            for (int r = 0; r < 4; r++) acc[mi][ni][r] = 0.f;

    uint32_t af[2][4][4], bf[2][8][2];

    auto loadfrag = [&](const float* As, const float* Bs, int kk, int buf) {
        int k = kk * 8;
#pragma unroll
        for (int mi = 0; mi < 4; mi++) {
            int mb = wm * 64 + mi * 16;
            af[buf][mi][0] = __float_as_uint(As[(mb + g) * PAD + k + tg]);
            af[buf][mi][1] = __float_as_uint(As[(mb + 8 + g) * PAD + k + tg]);
            af[buf][mi][2] = __float_as_uint(As[(mb + g) * PAD + k + 4 + tg]);
            af[buf][mi][3] = __float_as_uint(As[(mb + 8 + g) * PAD + k + 4 + tg]);
        }
#pragma unroll
        for (int ni = 0; ni < 8; ni++) {
            int nb = wn * 64 + ni * 8;
            bf[buf][ni][0] = tf32u(Bs[(nb + g) * PAD + k + tg]);
            bf[buf][ni][1] = tf32u(Bs[(nb + g) * PAD + k + 4 + tg]);
        }
    };

    const int NC = DFF / 32;  // 128
    issue(0); CP_COMMIT();
    issue(1); CP_COMMIT();
    issue(2); CP_COMMIT();

    for (int c = 0; c < NC; c++) {
        CP_WAIT2();
        __syncthreads();
        if (c + 3 < NC) issue(c + 3);
        CP_COMMIT();
        const float* As = (const float*)(dsm + (c % NSTAGE) * SSTAGE);
        const float* Bs = As + 18432 / 4;
        loadfrag(As, Bs, 0, 0);
#pragma unroll
        for (int kk = 0; kk < 4; kk++) {
            int cur = kk & 1;
            if (kk < 3) loadfrag(As, Bs, kk + 1, cur ^ 1);
#pragma unroll
            for (int ni = 0; ni < 8; ni++)
#pragma unroll
                for (int mi = 0; mi < 4; mi++)
                    mma_tf32(acc[mi][ni], af[cur][mi], bf[cur][ni][0], bf[cur][ni][1]);
        }
    }

    float* O = g_ob + (size_t)z * CAP * DM;
#pragma unroll
    for (int mi = 0; mi < 4; mi++)
#pragma unroll
        for (int half = 0; half < 2; half++) {
            int m = m0 + wm * 64 + mi * 16 + half * 8 + g;
            if (m < rows) {
#pragma unroll
                for (int ni = 0; ni < 8; ni++) {
                    int col = n0 + wn * 64 + ni * 8 + 2 * tg;
                    *(float2*)&O[(size_t)m * DM + col] =
                        make_float2(acc[mi][ni][half * 2 + 0], acc[mi][ni][half * 2 + 1]);
                }
            }
        }
}

// ---------------- 6. weighted scatter/combine ----------------
__global__ __launch_bounds__(256) void scatter_kernel(float* __restrict__ out) {
    int t = blockIdx.x;
    int d4 = threadIdx.x;
    float4 acc = {0.f, 0.f, 0.f, 0.f};
#pragma unroll
    for (int k = 0; k < TOPK; k++) {
        int tk = t * 2 + k;
        int pos = g_pos[tk];
        if (pos < CAP) {
            int e = g_top_idx[tk];
            float w = g_top_w[tk];
            float4 v = ((const float4*)(g_ob + ((size_t)(k * NE + e) * CAP + pos) * DM))[d4];
            acc.x += v.x * w; acc.y += v.y * w; acc.z += v.z * w; acc.w += v.w * w;
        }
    }
    ((float4*)(out + (size_t)t * DM))[d4] = acc;
}

// ---------------- 7. aux loss ----------------
__global__ __launch_bounds__(256) void aux_kernel(float* __restrict__ out, int out_size) {
    __shared__ float red[256];
    __shared__ float Ps[NE];
    int tid = threadIdx.x;
    float loc[NE];
#pragma unroll
    for (int e = 0; e < NE; e++) loc[e] = 0.f;
    for (int i = tid; i < N_TOK; i += 256) {
#pragma unroll
        for (int e = 0; e < NE; e++) loc[e] += g_probs[i * NE + e];
    }
    for (int e = 0; e < NE; e++) {
        red[tid] = loc[e];
        __syncthreads();
        for (int s = 128; s > 0; s >>= 1) {
            if (tid < s) red[tid] += red[tid + s];
            __syncthreads();
        }
        if (tid == 0) Ps[e] = red[0];
        __syncthreads();
    }
    if (tid == 0) {
        float aux = 0.f;
        for (int e = 0; e < NE; e++) {
            float f = (float)(g_cnt[e] + g_cnt[NE + e]) / (float)(N_TOK * TOPK);
            float P = Ps[e] / (float)N_TOK;
            aux += f * P;
        }
        out[out_size - 1] = aux * (float)NE;
    }
}

// ---------------- launch ----------------
extern "C" void kernel_launch(void* const* d_in, const int* in_sizes, int n_in,
                              void* d_out, int out_size) {
    const float* x  = (const float*)d_in[0];
    const float* gw = (const float*)d_in[1];
    const float* w1 = (const float*)d_in[2];
    const float* w2 = (const float*)d_in[3];
    const float* w3 = (const float*)d_in[4];
    float* out = (float*)d_out;

    const int SMEM = NSTAGE * SSTAGE;   // 221184
    cudaFuncSetAttribute(gemm13_mma, cudaFuncAttributeMaxDynamicSharedMemorySize, SMEM);
    cudaFuncSetAttribute(gemm2_mma,  cudaFuncAttributeMaxDynamicSharedMemorySize, SMEM);

    router_kernel<<<N_TOK / 8, 256>>>(x, gw);
    scan_kernel<<<2, 256>>>();
    gather_kernel<<<N_TOK * TOPK, 256>>>(x);

    dim3 g1(DFF / 128, CAP / 128, TOPK * NE);   // 32 x 10 x 16
    gemm13_mma<<<g1, 256, SMEM>>>(w1, w3);

    dim3 g2(DM / 256, CAP / 128, TOPK * NE);    // 4 x 10 x 16
    gemm2_mma<<<g2, 256, SMEM>>>(w2);

    scatter_kernel<<<N_TOK, 256>>>(out);
    aux_kernel<<<1, 256>>>(out, out_size);
}